// round 2
// baseline (speedup 1.0000x reference)
#include <cuda_runtime.h>
#include <cstdint>

// Problem dims
#define T_STEPS 512
#define BD 64          // batch
#define ID 256         // input dim
#define HD 1024        // hidden dim
#define OD 256         // output dim
#define NG 4096        // 4*H gate rows
#define NTOT 4352      // gate rows + out rows
#define KD 1280        // I + H
#define NPC 32         // N columns per CTA
#define NCTA 136       // NTOT / NPC
#define KC 32          // K chunk size
#define NCHUNK 40      // KD / KC
#define SPAD 4         // smem row padding (floats)

// Persistent device scratch (allocation-free rule: __device__ globals)
__device__ float g_Wcat[(size_t)NTOT * KD];          // [4352][1280] tf32-rounded, row r = 4*j+gate (or 4096+o)
__device__ float g_xr[(size_t)T_STEPS * BD * ID];    // tf32-rounded copy of x
__device__ float g_bias[NTOT];                       // b_ih+b_hh (reordered) | b_out
__device__ float g_h[2][BD * HD];                    // ping-pong hidden state (tf32-rounded)
__device__ float g_c[BD * HD];                       // cell state (fp32)

__device__ __forceinline__ uint32_t f2tf(float f) {
    uint32_t u;
    asm("cvt.rna.tf32.f32 %0, %1;" : "=r"(u) : "f"(f));
    return u;
}

__device__ __forceinline__ void cpasync16(uint32_t smem, const void* gmem) {
    asm volatile("cp.async.cg.shared.global [%0], [%1], 16;\n" :: "r"(smem), "l"(gmem));
}

// ---------------------------------------------------------------------------
// Prep: build reordered+rounded W_cat, rounded x copy, bias, zero h/c.
// Runs at the start of every graph replay (deterministic).
// ---------------------------------------------------------------------------
__global__ void prep_kernel(const float* __restrict__ x,
                            const float* __restrict__ W_ih,
                            const float* __restrict__ W_hh,
                            const float* __restrict__ b_ih,
                            const float* __restrict__ b_hh,
                            const float* __restrict__ W_out,
                            const float* __restrict__ b_out)
{
    const size_t S_W = (size_t)NTOT * KD;
    const size_t S_X = S_W + (size_t)T_STEPS * BD * ID;
    const size_t S_B = S_X + NTOT;
    const size_t S_H = S_B + 2 * BD * HD;
    const size_t S_C = S_H + BD * HD;
    for (size_t i = (size_t)blockIdx.x * blockDim.x + threadIdx.x; i < S_C;
         i += (size_t)gridDim.x * blockDim.x) {
        if (i < S_W) {
            size_t r = i / KD, k = i % KD;
            float v;
            if (r < NG) {
                int j = (int)(r >> 2), g = (int)(r & 3);
                int orig = g * HD + j;    // PyTorch order: i,f,g,o blocks
                v = (k < ID) ? W_ih[(size_t)orig * ID + k]
                             : W_hh[(size_t)orig * HD + (k - ID)];
            } else {
                int o = (int)(r - NG);
                v = (k < ID) ? 0.0f : W_out[(size_t)o * HD + (k - ID)];
            }
            g_Wcat[i] = __uint_as_float(f2tf(v));
        } else if (i < S_X) {
            size_t j = i - S_W;
            g_xr[j] = __uint_as_float(f2tf(x[j]));
        } else if (i < S_B) {
            size_t r = i - S_X;
            float v;
            if (r < NG) {
                int j = (int)(r >> 2), g = (int)(r & 3);
                int orig = g * HD + j;
                v = b_ih[orig] + b_hh[orig];
            } else {
                v = b_out[r - NG];
            }
            g_bias[r] = v;
        } else if (i < S_H) {
            ((float*)g_h)[i - S_B] = 0.0f;
        } else {
            g_c[i - S_H] = 0.0f;
        }
    }
}

// ---------------------------------------------------------------------------
// One recurrent step. Fused: gates GEMM + LSTM elementwise + out[t-1] GEMM.
// Grid: 136 CTAs x 128 threads. CTA b covers N columns [32b, 32b+32).
// Step t: reads h_{t-1} from g_h[t&1], writes h_t to g_h[(t+1)&1].
// CTAs with n0 >= 4096 compute out[t-1] (valid for t >= 1).
// t == T_STEPS: only the out block runs (emits out[T-1]).
// ---------------------------------------------------------------------------
__global__ void __launch_bounds__(128) step_kernel(int t, float* __restrict__ out)
{
    __shared__ __align__(16) float sA[2][BD][KC + SPAD];    // 18.4 KB
    __shared__ __align__(16) float sW[2][NPC][KC + SPAD];   //  9.2 KB

    const int tid = threadIdx.x;
    const int w = tid >> 5;
    const int lane = tid & 31;
    const int G = lane >> 2;     // groupID
    const int tg = lane & 3;     // threadID_in_group
    const int n0 = blockIdx.x * NPC;
    const bool is_out = (n0 >= NG);

    if (is_out && t == 0) return;
    if (!is_out && t == T_STEPS) return;

    const float* __restrict__ hsrc = g_h[t & 1];

    // Accumulators, init with bias (C-frag col = n0 + nt*8 + 2*tg (+1))
    float acc[4][4];
#pragma unroll
    for (int nt = 0; nt < 4; nt++) {
        float b0 = g_bias[n0 + nt * 8 + 2 * tg];
        float b1 = g_bias[n0 + nt * 8 + 2 * tg + 1];
        acc[nt][0] = b0; acc[nt][1] = b1;
        acc[nt][2] = b0; acc[nt][3] = b1;
    }

    // --- staging: chunk kc into buffer buf ---
    auto stage = [&](int kc, int buf) {
        const int k0 = kc * KC;
        // A tile: 64 rows x 32 cols = 512 float4 segments
#pragma unroll
        for (int it = 0; it < 4; it++) {
            int i = tid + it * 128;          // 0..511
            int row = i >> 3, v = i & 7;
            int kk = k0 + v * 4;
            uint32_t dst = (uint32_t)__cvta_generic_to_shared(&sA[buf][row][v * 4]);
            if (kk < ID) {
                if (t < T_STEPS) {
                    cpasync16(dst, &g_xr[((size_t)t * BD + row) * ID + kk]);
                } else {
                    *(float4*)&sA[buf][row][v * 4] = make_float4(0.f, 0.f, 0.f, 0.f);
                }
            } else {
                cpasync16(dst, &hsrc[row * HD + (kk - ID)]);
            }
        }
        // W tile: 32 rows x 32 cols = 256 float4 segments
#pragma unroll
        for (int it = 0; it < 2; it++) {
            int i = tid + it * 128;          // 0..255
            int row = i >> 3, v = i & 7;
            uint32_t dst = (uint32_t)__cvta_generic_to_shared(&sW[buf][row][v * 4]);
            cpasync16(dst, &g_Wcat[(size_t)(n0 + row) * KD + k0 + v * 4]);
        }
    };

    stage(0, 0);
    asm volatile("cp.async.commit_group;");

#pragma unroll 1
    for (int kc = 0; kc < NCHUNK; kc++) {
        const int buf = kc & 1;
        if (kc + 1 < NCHUNK) {
            stage(kc + 1, buf ^ 1);
            asm volatile("cp.async.commit_group;");
            asm volatile("cp.async.wait_group 1;");
        } else {
            asm volatile("cp.async.wait_group 0;");
        }
        __syncthreads();

#pragma unroll
        for (int ki = 0; ki < KC / 8; ki++) {
            const int k = ki * 8;
            // A fragment (m16n8k8.tf32 layout), cvt.rna on the fly
            uint32_t a0 = f2tf(sA[buf][16 * w + G][k + tg]);
            uint32_t a1 = f2tf(sA[buf][16 * w + G + 8][k + tg]);
            uint32_t a2 = f2tf(sA[buf][16 * w + G][k + tg + 4]);
            uint32_t a3 = f2tf(sA[buf][16 * w + G + 8][k + tg + 4]);
#pragma unroll
            for (int nt = 0; nt < 4; nt++) {
                uint32_t b0 = __float_as_uint(sW[buf][nt * 8 + G][k + tg]);
                uint32_t b1 = __float_as_uint(sW[buf][nt * 8 + G][k + tg + 4]);
                asm volatile(
                    "mma.sync.aligned.m16n8k8.row.col.f32.tf32.tf32.f32 "
                    "{%0,%1,%2,%3},{%4,%5,%6,%7},{%8,%9},{%0,%1,%2,%3};"
                    : "+f"(acc[nt][0]), "+f"(acc[nt][1]),
                      "+f"(acc[nt][2]), "+f"(acc[nt][3])
                    : "r"(a0), "r"(a1), "r"(a2), "r"(a3), "r"(b0), "r"(b1));
            }
        }
        __syncthreads();
    }

    if (!is_out) {
        // Dump gates to smem (reuse sA[0]: 64 x 36 floats)
        float (*gs)[KC + SPAD] = sA[0];
#pragma unroll
        for (int nt = 0; nt < 4; nt++) {
            int col = nt * 8 + 2 * tg;
            gs[16 * w + G][col]         = acc[nt][0];
            gs[16 * w + G][col + 1]     = acc[nt][1];
            gs[16 * w + G + 8][col]     = acc[nt][2];
            gs[16 * w + G + 8][col + 1] = acc[nt][3];
        }
        __syncthreads();

        float* __restrict__ hdst = g_h[(t + 1) & 1];
        const int jbase = n0 >> 2;   // 8 hidden units per CTA
#pragma unroll
        for (int it = 0; it < 4; it++) {
            int p = tid + it * 128;          // 0..511 = 64 batch x 8 units
            int jl = p & 7, b = p >> 3;
            float ig = gs[b][4 * jl + 0];
            float fg = gs[b][4 * jl + 1];
            float gg = gs[b][4 * jl + 2];
            float og = gs[b][4 * jl + 3];
            ig = 1.0f / (1.0f + expf(-ig));
            fg = 1.0f / (1.0f + expf(-fg));
            og = 1.0f / (1.0f + expf(-og));
            gg = tanhf(gg);
            int idx = b * HD + jbase + jl;
            float c = fg * g_c[idx] + ig * gg;
            g_c[idx] = c;
            float h = og * tanhf(c);
            hdst[idx] = __uint_as_float(f2tf(h));   // pre-round: h only feeds tf32 GEMMs
        }
    } else {
        // Output block: rows are out[t-1][b][col]
        const int ob = n0 - NG;
        float* __restrict__ dst = out + (size_t)(t - 1) * BD * OD;
#pragma unroll
        for (int nt = 0; nt < 4; nt++) {
            int col = ob + nt * 8 + 2 * tg;
            int r0 = 16 * w + G, r1 = r0 + 8;
            dst[r0 * OD + col]     = acc[nt][0];
            dst[r0 * OD + col + 1] = acc[nt][1];
            dst[r1 * OD + col]     = acc[nt][2];
            dst[r1 * OD + col + 1] = acc[nt][3];
        }
    }
}

// ---------------------------------------------------------------------------
extern "C" void kernel_launch(void* const* d_in, const int* in_sizes, int n_in,
                              void* d_out, int out_size)
{
    const float* x     = (const float*)d_in[0];
    const float* W_ih  = (const float*)d_in[1];
    const float* W_hh  = (const float*)d_in[2];
    const float* b_ih  = (const float*)d_in[3];
    const float* b_hh  = (const float*)d_in[4];
    const float* W_out = (const float*)d_in[5];
    const float* b_out = (const float*)d_in[6];
    float* out = (float*)d_out;

    prep_kernel<<<2048, 256>>>(x, W_ih, W_hh, b_ih, b_hh, W_out, b_out);
    for (int t = 0; t <= T_STEPS; t++) {
        step_kernel<<<NCTA, 128>>>(t, out);
    }
}

// round 4
// speedup vs baseline: 1.2730x; 1.2730x over previous
#include <cuda_runtime.h>
#include <cstdint>

#define T_STEPS 512
#define BD 64
#define ID 256
#define HD 1024
#define OD 256
#define NG 4096
#define NTOT 4352
#define KD 1280
#define NPC 32
#define NCTA 136
#define KC 64
#define NCHUNK 20
#define KCPAD 68
#define NKI 160                         // KD / 8

#define SW_FLOATS (NKI * 2 * 32 * 4)    // 40960 (W fragments)
#define SA_FLOATS (3 * BD * KCPAD)      // 13056 (triple-buffered A tile)
#define SMEM_BYTES ((SW_FLOATS + SA_FLOATS) * 4)   // 216064 B

// Persistent device scratch (allocation-free rule: __device__ globals)
__device__ float g_xr[(size_t)T_STEPS * BD * ID];  // tf32-rounded x, pair-packed within 8-groups
__device__ float g_h[2][BD * HD];                  // ping-pong hidden state (rounded, pair-packed)
__device__ float g_c[BD * HD];                     // cell state (fp32)
__device__ unsigned g_arrive;                      // grid barrier counter

__device__ __forceinline__ uint32_t f2tf(float f) {
    uint32_t u;
    asm("cvt.rna.tf32.f32 %0, %1;" : "=r"(u) : "f"(f));
    return u;
}
__device__ __forceinline__ float f2tff(float f) { return __uint_as_float(f2tf(f)); }

__device__ __forceinline__ void cpasync16(uint32_t smem, const void* gmem) {
    asm volatile("cp.async.cg.shared.global [%0], [%1], 16;\n" :: "r"(smem), "l"(gmem));
}

// ---------------------------------------------------------------------------
// Prep: rounded+permuted x copy, zero h/c, reset barrier counter.
// Pair-pack permutation WITHIN each 8-group: offset cg -> 2*(cg&3) + (cg>>2).
// (Round-3 bug: used (c>>2) with c the full row offset instead of cg&7's bit.)
// ---------------------------------------------------------------------------
__global__ void prep_kernel(const float* __restrict__ x)
{
    const size_t S_X = (size_t)T_STEPS * BD * ID;
    const size_t S_H = S_X + 2 * BD * HD;
    const size_t S_C = S_H + BD * HD;
    for (size_t i = (size_t)blockIdx.x * blockDim.x + threadIdx.x; i < S_C;
         i += (size_t)gridDim.x * blockDim.x) {
        if (i == 0) g_arrive = 0;
        if (i < S_X) {
            int c = (int)(i & 255);             // ID == 256
            int cg = c & 7;                     // within-8-group offset
            size_t base = i - (size_t)c;
            g_xr[base + (c & ~7) + 2 * (cg & 3) + (cg >> 2)] = f2tff(x[i]);
        } else if (i < S_H) {
            ((float*)g_h)[i - S_X] = 0.0f;
        } else {
            g_c[i - S_H] = 0.0f;
        }
    }
}

// ---------------------------------------------------------------------------
// Persistent LSTM kernel. 136 CTAs x 256 threads, one CTA per SM.
// CTA b owns gate rows [32b, 32b+32) (reordered r = 4*j + gate) or, for the
// last 8 CTAs, output rows (out projection folded as extra N columns).
// W slice lives in smem in per-lane MMA fragment layout for the whole run.
// ---------------------------------------------------------------------------
__global__ void __launch_bounds__(256, 1) lstm_kernel(
    const float* __restrict__ W_ih, const float* __restrict__ W_hh,
    const float* __restrict__ b_ih, const float* __restrict__ b_hh,
    const float* __restrict__ W_out, const float* __restrict__ b_out,
    float* __restrict__ out)
{
    extern __shared__ float sm[];
    float* sW = sm;                    // [NKI][2][32 lanes][4]  (fragment layout)
    float* sA = sm + SW_FLOATS;        // [3][BD][KCPAD]

    const int tid = threadIdx.x;
    const int lane = tid & 31, w = tid >> 5;
    const int wm = w & 3, wn = w >> 2;          // M-group / N-group of this warp
    const int G = lane >> 2, tg = lane & 3;
    const int n0 = blockIdx.x * NPC;
    const bool is_out = (n0 >= NG);
    const int r0 = 16 * wm + G;

    // ---- Build W fragments in smem (once). Coalesced float4 row reads. ----
    {
        const int r = tid >> 3;                 // local row 0..31
        const int cth = tid & 7;
        const int rowg = n0 + r;
        const int nt = r >> 3, Gr = r & 7;
#pragma unroll 1
        for (int u = 0; u < KD / 32; u++) {
            int col0 = cth * 4 + u * 32;
            float4 v;
            if (rowg < NG) {
                int orig = (rowg & 3) * HD + (rowg >> 2);   // PyTorch i,f,g,o blocks
                if (col0 < ID) v = *(const float4*)&W_ih[(size_t)orig * ID + col0];
                else           v = *(const float4*)&W_hh[(size_t)orig * HD + (col0 - ID)];
            } else {
                if (col0 < ID) v = make_float4(0.f, 0.f, 0.f, 0.f);
                else           v = *(const float4*)&W_out[(size_t)(rowg - NG) * HD + (col0 - ID)];
            }
            float vv[4] = {v.x, v.y, v.z, v.w};
#pragma unroll
            for (int e = 0; e < 4; e++) {
                int col = col0 + e;
                int ki = col >> 3, cw = col & 7;
                int tgc = cw & 3, half = cw >> 2;
                int idx = ((ki * 2 + (nt >> 1)) * 32 + (Gr * 4 + tgc)) * 4 + (nt & 1) * 2 + half;
                sW[idx] = f2tff(vv[e]);
            }
        }
    }

    // ---- Bias fragment (per lane, 2 nt x 2 cols) ----
    float bs[2][2];
#pragma unroll
    for (int ntl = 0; ntl < 2; ntl++) {
#pragma unroll
        for (int e = 0; e < 2; e++) {
            int rr = n0 + (2 * wn + ntl) * 8 + 2 * tg + e;
            float bv;
            if (rr < NG) {
                int orig = (rr & 3) * HD + (rr >> 2);
                bv = b_ih[orig] + b_hh[orig];
            } else {
                bv = b_out[rr - NG];
            }
            bs[ntl][e] = bv;
        }
    }
    __syncthreads();

    // ---- Time loop ----
    for (int t = 0; t <= T_STEPS; t++) {
        const bool active = is_out ? (t > 0) : (t < T_STEPS);
        if (active) {
            const float* __restrict__ hsrc = g_h[t & 1];

            auto stage = [&](int kc) {
                float* dstbuf = sA + (kc % 3) * (BD * KCPAD);
                const int k0 = kc * KC;
#pragma unroll
                for (int it = 0; it < 4; it++) {
                    int i = tid + it * 256;          // 0..1023
                    int row = i >> 4, v = i & 15;
                    int col = k0 + v * 4;
                    float* d = dstbuf + row * KCPAD + v * 4;
                    if (col < ID) {
                        if (t < T_STEPS)
                            cpasync16((uint32_t)__cvta_generic_to_shared(d),
                                      &g_xr[((size_t)t * BD + row) * ID + col]);
                        else
                            *(float4*)d = make_float4(0.f, 0.f, 0.f, 0.f);
                    } else {
                        cpasync16((uint32_t)__cvta_generic_to_shared(d),
                                  &hsrc[row * HD + (col - ID)]);
                    }
                }
            };

            float acc[2][4];
#pragma unroll
            for (int ntl = 0; ntl < 2; ntl++) {
                acc[ntl][0] = bs[ntl][0]; acc[ntl][1] = bs[ntl][1];
                acc[ntl][2] = bs[ntl][0]; acc[ntl][3] = bs[ntl][1];
            }

            stage(0);
            asm volatile("cp.async.commit_group;");

#pragma unroll 1
            for (int kc = 0; kc < NCHUNK; kc++) {
                if (kc + 1 < NCHUNK) stage(kc + 1);
                asm volatile("cp.async.commit_group;");
                asm volatile("cp.async.wait_group 1;");
                __syncthreads();
                const float* buf = sA + (kc % 3) * (BD * KCPAD);
#pragma unroll
                for (int kil = 0; kil < 8; kil++) {
                    int kiG = kc * 8 + kil;
                    float4 B = *(const float4*)&sW[((kiG * 2 + wn) * 32 + lane) * 4];
                    float2 aL = *(const float2*)&buf[r0 * KCPAD + kil * 8 + 2 * tg];
                    float2 aH = *(const float2*)&buf[(r0 + 8) * KCPAD + kil * 8 + 2 * tg];
                    uint32_t a0 = __float_as_uint(aL.x), a2 = __float_as_uint(aL.y);
                    uint32_t a1 = __float_as_uint(aH.x), a3 = __float_as_uint(aH.y);
                    asm volatile(
                        "mma.sync.aligned.m16n8k8.row.col.f32.tf32.tf32.f32 "
                        "{%0,%1,%2,%3},{%4,%5,%6,%7},{%8,%9},{%0,%1,%2,%3};"
                        : "+f"(acc[0][0]), "+f"(acc[0][1]), "+f"(acc[0][2]), "+f"(acc[0][3])
                        : "r"(a0), "r"(a1), "r"(a2), "r"(a3),
                          "r"(__float_as_uint(B.x)), "r"(__float_as_uint(B.y)));
                    asm volatile(
                        "mma.sync.aligned.m16n8k8.row.col.f32.tf32.tf32.f32 "
                        "{%0,%1,%2,%3},{%4,%5,%6,%7},{%8,%9},{%0,%1,%2,%3};"
                        : "+f"(acc[1][0]), "+f"(acc[1][1]), "+f"(acc[1][2]), "+f"(acc[1][3])
                        : "r"(a0), "r"(a1), "r"(a2), "r"(a3),
                          "r"(__float_as_uint(B.z)), "r"(__float_as_uint(B.w)));
                }
            }

            if (!is_out) {
                // Gates -> smem (reuse A buffer 0 region), then LSTM elementwise.
                __syncthreads();
                float (*gs)[36] = (float(*)[36])sA;
#pragma unroll
                for (int ntl = 0; ntl < 2; ntl++) {
                    int colc = (2 * wn + ntl) * 8 + 2 * tg;
                    gs[r0][colc]         = acc[ntl][0];
                    gs[r0][colc + 1]     = acc[ntl][1];
                    gs[r0 + 8][colc]     = acc[ntl][2];
                    gs[r0 + 8][colc + 1] = acc[ntl][3];
                }
                __syncthreads();

                float* __restrict__ hdst = g_h[(t + 1) & 1];
                const int jbase = n0 >> 2;          // 8 hidden units per CTA
#pragma unroll
                for (int it = 0; it < 2; it++) {
                    int p = tid + it * 256;          // 0..511 = 64 batch x 8 units
                    int jl = p & 7, b = p >> 3;
                    float ig = gs[b][4 * jl + 0];
                    float fg = gs[b][4 * jl + 1];
                    float gg = gs[b][4 * jl + 2];
                    float og = gs[b][4 * jl + 3];
                    ig = 1.0f / (1.0f + __expf(-ig));
                    fg = 1.0f / (1.0f + __expf(-fg));
                    og = 1.0f / (1.0f + __expf(-og));
                    gg = tanhf(gg);
                    int idx = b * HD + jbase + jl;
                    float c = fg * g_c[idx] + ig * gg;
                    g_c[idx] = c;
                    // store pair-packed + rounded (h only feeds tf32 GEMMs)
                    hdst[b * HD + jbase + 2 * (jl & 3) + (jl >> 2)] =
                        f2tff(og * tanhf(c));
                }
            } else {
                const int ob = n0 - NG;
                float* __restrict__ dst = out + (size_t)(t - 1) * BD * OD;
#pragma unroll
                for (int ntl = 0; ntl < 2; ntl++) {
                    int colc = ob + (2 * wn + ntl) * 8 + 2 * tg;
                    dst[r0 * OD + colc]           = acc[ntl][0];
                    dst[r0 * OD + colc + 1]       = acc[ntl][1];
                    dst[(r0 + 8) * OD + colc]     = acc[ntl][2];
                    dst[(r0 + 8) * OD + colc + 1] = acc[ntl][3];
                }
            }
        }

        if (t == T_STEPS) break;

        // ---- grid barrier (release-acquire, all 136 CTAs co-resident) ----
        __syncthreads();
        if (tid == 0) {
            __threadfence();
            atomicAdd(&g_arrive, 1u);
            const unsigned target = (unsigned)(t + 1) * NCTA;
            unsigned v;
            do {
                asm volatile("ld.acquire.gpu.u32 %0, [%1];" : "=r"(v) : "l"(&g_arrive));
            } while (v < target);
        }
        __syncthreads();
    }
}

// ---------------------------------------------------------------------------
extern "C" void kernel_launch(void* const* d_in, const int* in_sizes, int n_in,
                              void* d_out, int out_size)
{
    const float* x     = (const float*)d_in[0];
    const float* W_ih  = (const float*)d_in[1];
    const float* W_hh  = (const float*)d_in[2];
    const float* b_ih  = (const float*)d_in[3];
    const float* b_hh  = (const float*)d_in[4];
    const float* W_out = (const float*)d_in[5];
    const float* b_out = (const float*)d_in[6];
    float* out = (float*)d_out;

    cudaFuncSetAttribute(lstm_kernel,
                         cudaFuncAttributeMaxDynamicSharedMemorySize, SMEM_BYTES);
    prep_kernel<<<1024, 256>>>(x);
    lstm_kernel<<<NCTA, 256, SMEM_BYTES>>>(W_ih, W_hh, b_ih, b_hh, W_out, b_out, out);
}

// round 6
// speedup vs baseline: 1.2798x; 1.0054x over previous
#include <cuda_runtime.h>
#include <cstdint>

#define T_STEPS 512
#define BD 64
#define ID 256
#define HD 1024
#define OD 256
#define NG 4096
#define NTOT 4352
#define KD 1280
#define NPC 32
#define NCTA 136
#define KC 64
#define NCHUNK 20
#define KCPAD 68
#define NKI 160                         // KD / 8

#define SW_FLOATS (NKI * 2 * 32 * 4)    // 40960 floats = 160KB (W fragments)
#define SA_FLOATS (3 * BD * KCPAD)      // 13056 floats (triple-buffered A tile)
#define SMEM_BYTES ((SW_FLOATS + SA_FLOATS) * 4)   // 216064 B
#define RED_PITCH 17                    // reduction row pitch (floats)

// Persistent device scratch (allocation-free rule: __device__ globals)
__device__ float g_xr[(size_t)T_STEPS * BD * ID];  // tf32-rounded x, pair-packed within 8-groups
__device__ float g_h[2][BD * HD];                  // ping-pong hidden state (rounded, pair-packed)
__device__ unsigned g_arrive;                      // grid barrier counter

__device__ __forceinline__ uint32_t f2tf(float f) {
    uint32_t u;
    asm("cvt.rna.tf32.f32 %0, %1;" : "=r"(u) : "f"(f));
    return u;
}
__device__ __forceinline__ float f2tff(float f) { return __uint_as_float(f2tf(f)); }

__device__ __forceinline__ void cpasync16(uint32_t smem, const void* gmem) {
    asm volatile("cp.async.cg.shared.global [%0], [%1], 16;\n" :: "r"(smem), "l"(gmem));
}

// ---------------------------------------------------------------------------
// Prep: rounded+permuted x copy, zero h, reset barrier counter.
// Pair-pack permutation WITHIN each 8-group: offset cg -> 2*(cg&3) + (cg>>2).
// ---------------------------------------------------------------------------
__global__ void prep_kernel(const float* __restrict__ x)
{
    const size_t S_X = (size_t)T_STEPS * BD * ID;
    const size_t S_H = S_X + 2 * BD * HD;
    for (size_t i = (size_t)blockIdx.x * blockDim.x + threadIdx.x; i < S_H;
         i += (size_t)gridDim.x * blockDim.x) {
        if (i == 0) g_arrive = 0;
        if (i < S_X) {
            int c = (int)(i & 255);             // ID == 256
            int cg = c & 7;                     // within-8-group offset
            size_t base = i - (size_t)c;
            g_xr[base + (c & ~7) + 2 * (cg & 3) + (cg >> 2)] = f2tff(x[i]);
        } else {
            ((float*)g_h)[i - S_X] = 0.0f;
        }
    }
}

// ---------------------------------------------------------------------------
// Persistent LSTM kernel. 136 CTAs x 256 threads (8 warps), one CTA per SM.
// CTA b owns gate rows [32b, 32b+32) (reordered r = 4*j+gate) or, for the
// last 8 CTAs, output-projection rows.
// K-SPLIT: each warp computes the FULL 64x32 tile over a disjoint K slice
// (warp w handles k-slice w of each 64-wide chunk); 8 partial accumulators
// are reduced through smem in two N-halves at the end of each step.
// ---------------------------------------------------------------------------
__global__ void __launch_bounds__(256, 1) lstm_kernel(
    const float* __restrict__ W_ih, const float* __restrict__ W_hh,
    const float* __restrict__ b_ih, const float* __restrict__ b_hh,
    const float* __restrict__ W_out, const float* __restrict__ b_out,
    float* __restrict__ out)
{
    extern __shared__ float sm[];
    float* sW = sm;                    // [NKI][2][32 lanes][4]  (fragment layout)
    float* sA = sm + SW_FLOATS;        // [3][BD][KCPAD]; also reduction buffer

    const int tid = threadIdx.x;
    const int lane = tid & 31, w = tid >> 5;
    const int G = lane >> 2, tg = lane & 3;
    const int n0 = blockIdx.x * NPC;
    const bool is_out = (n0 >= NG);

    // ---- Build W fragments in smem (once). Coalesced float4 row reads. ----
    {
        const int r = tid >> 3;                 // local row 0..31
        const int cth = tid & 7;
        const int rowg = n0 + r;
        const int nt = r >> 3, Gr = r & 7;
#pragma unroll 1
        for (int u = 0; u < KD / 32; u++) {
            int col0 = cth * 4 + u * 32;
            float4 v;
            if (rowg < NG) {
                int orig = (rowg & 3) * HD + (rowg >> 2);   // PyTorch i,f,g,o blocks
                if (col0 < ID) v = *(const float4*)&W_ih[(size_t)orig * ID + col0];
                else           v = *(const float4*)&W_hh[(size_t)orig * HD + (col0 - ID)];
            } else {
                if (col0 < ID) v = make_float4(0.f, 0.f, 0.f, 0.f);
                else           v = *(const float4*)&W_out[(size_t)(rowg - NG) * HD + (col0 - ID)];
            }
            float vv[4] = {v.x, v.y, v.z, v.w};
#pragma unroll
            for (int e = 0; e < 4; e++) {
                int col = col0 + e;
                int ki = col >> 3, cw = col & 7;
                int tgc = cw & 3, half = cw >> 2;
                int idx = ((ki * 2 + (nt >> 1)) * 32 + (Gr * 4 + tgc)) * 4 + (nt & 1) * 2 + half;
                sW[idx] = f2tff(vv[e]);
            }
        }
    }

    // ---- Per-thread epilogue bias: thread (b=tid>>2, u=tid&3), cols 4u+g ----
    float bias[2][4];
#pragma unroll
    for (int hn = 0; hn < 2; hn++) {
#pragma unroll
        for (int g = 0; g < 4; g++) {
            int rr = n0 + hn * 16 + 4 * (tid & 3) + g;
            float bv;
            if (rr < NG) {
                int orig = (rr & 3) * HD + (rr >> 2);
                bv = b_ih[orig] + b_hh[orig];
            } else bv = b_out[rr - NG];
            bias[hn][g] = bv;
        }
    }
    float cstate[2] = {0.0f, 0.0f};    // c for (b, jl=4*hn+u)
    __syncthreads();

    // ---- Time loop ----
    for (int t = 0; t <= T_STEPS; t++) {
        const bool active = is_out ? (t > 0) : (t < T_STEPS);
        if (active) {
            const int tx = (t < T_STEPS) ? t : (T_STEPS - 1);  // W=0 over x-range for out rows
            const float* __restrict__ hsrc = g_h[t & 1];

            auto stage = [&](int kc) {
                float* dstbuf = sA + (kc % 3) * (BD * KCPAD);
                const int k0 = kc * KC;
#pragma unroll
                for (int it = 0; it < 4; it++) {
                    int i = tid + it * 256;          // 0..1023
                    int row = i >> 4, v = i & 15;
                    int col = k0 + v * 4;
                    float* d = dstbuf + row * KCPAD + v * 4;
                    const float* src = (col < ID)
                        ? &g_xr[((size_t)tx * BD + row) * ID + col]
                        : &hsrc[row * HD + (col - ID)];
                    cpasync16((uint32_t)__cvta_generic_to_shared(d), src);
                }
            };

            float acc[4][4][4];                     // [m-tile][n-tile][frag]
#pragma unroll
            for (int m = 0; m < 4; m++)
#pragma unroll
                for (int n = 0; n < 4; n++)
#pragma unroll
                    for (int e = 0; e < 4; e++) acc[m][n][e] = 0.0f;

            stage(0);
            asm volatile("cp.async.commit_group;");

#pragma unroll 1
            for (int kc = 0; kc < NCHUNK; kc++) {
                if (kc + 1 < NCHUNK) {
                    stage(kc + 1);
                    asm volatile("cp.async.commit_group;");
                    asm volatile("cp.async.wait_group 1;");
                } else {
                    asm volatile("cp.async.wait_group 0;");
                }
                __syncthreads();
                const float* buf = sA + (kc % 3) * (BD * KCPAD);
                const int kiG = kc * 8 + w;         // this warp's k-slice
                float4 B0 = *(const float4*)&sW[((kiG * 2 + 0) * 32 + lane) * 4];
                float4 B1 = *(const float4*)&sW[((kiG * 2 + 1) * 32 + lane) * 4];
#pragma unroll
                for (int m = 0; m < 4; m++) {
                    int r = 16 * m + G;
                    float2 aL = *(const float2*)&buf[r * KCPAD + w * 8 + 2 * tg];
                    float2 aH = *(const float2*)&buf[(r + 8) * KCPAD + w * 8 + 2 * tg];
                    uint32_t a0 = __float_as_uint(aL.x), a2 = __float_as_uint(aL.y);
                    uint32_t a1 = __float_as_uint(aH.x), a3 = __float_as_uint(aH.y);
#define MMA1(ACC, B0R, B1R)                                                     \
    asm volatile(                                                               \
        "mma.sync.aligned.m16n8k8.row.col.f32.tf32.tf32.f32 "                   \
        "{%0,%1,%2,%3},{%4,%5,%6,%7},{%8,%9},{%0,%1,%2,%3};"                    \
        : "+f"(ACC[0]), "+f"(ACC[1]), "+f"(ACC[2]), "+f"(ACC[3])                \
        : "r"(a0), "r"(a1), "r"(a2), "r"(a3), "r"(B0R), "r"(B1R))
                    MMA1(acc[m][0], __float_as_uint(B0.x), __float_as_uint(B0.y));
                    MMA1(acc[m][1], __float_as_uint(B0.z), __float_as_uint(B0.w));
                    MMA1(acc[m][2], __float_as_uint(B1.x), __float_as_uint(B1.y));
                    MMA1(acc[m][3], __float_as_uint(B1.z), __float_as_uint(B1.w));
#undef MMA1
                }
            }
            __syncthreads();    // all warps done reading A stages before reuse

            // ---- 8-way reduction + epilogue, two N-halves of 16 cols ----
            float* sRed = sA;   // 8 warps x [64 rows x pitch17] = 34816 floats? no: 8*64*17=8704 floats
            const int b = tid >> 2, u = tid & 3;
#pragma unroll 1
            for (int hn = 0; hn < 2; hn++) {
                // scatter partials: warp w rows, cols hn*16 + [0,16)
#pragma unroll
                for (int m = 0; m < 4; m++)
#pragma unroll
                    for (int nl = 0; nl < 2; nl++)
#pragma unroll
                        for (int e = 0; e < 4; e++) {
                            int row = 16 * m + G + (e >> 1) * 8;
                            int ch = nl * 8 + 2 * tg + (e & 1);
                            sRed[(w * BD + row) * RED_PITCH + ch] = acc[m][2 * hn + nl][e];
                        }
                __syncthreads();
                // reduce: thread (b,u) sums 8 warps for its 4 gate cols
                float gv[4];
#pragma unroll
                for (int g = 0; g < 4; g++) {
                    float s = 0.0f;
#pragma unroll
                    for (int ww = 0; ww < 8; ww++)
                        s += sRed[(ww * BD + b) * RED_PITCH + 4 * u + g];
                    gv[g] = s + bias[hn][g];
                }
                if (!is_out) {
                    float ig = 1.0f / (1.0f + __expf(-gv[0]));
                    float fg = 1.0f / (1.0f + __expf(-gv[1]));
                    float gg = tanhf(gv[2]);
                    float og = 1.0f / (1.0f + __expf(-gv[3]));
                    float cv = fg * cstate[hn] + ig * gg;
                    cstate[hn] = cv;
                    int jl = 4 * hn + u;
                    int jbase = n0 >> 2;
                    g_h[(t + 1) & 1][b * HD + jbase + 2 * (jl & 3) + (jl >> 2)] =
                        f2tff(og * tanhf(cv));
                } else {
                    float* __restrict__ dst = out + (size_t)(t - 1) * BD * OD;
                    int col = (n0 - NG) + hn * 16 + 4 * u;
                    *(float4*)&dst[(size_t)b * OD + col] =
                        make_float4(gv[0], gv[1], gv[2], gv[3]);
                }
                __syncthreads();
            }
        }

        if (t == T_STEPS) break;

        // ---- grid barrier (136 CTAs co-resident) ----
        __syncthreads();
        if (tid == 0) {
            __threadfence();
            atomicAdd(&g_arrive, 1u);
            const unsigned target = (unsigned)(t + 1) * NCTA;
            unsigned v;
            do {
                asm volatile("ld.acquire.gpu.u32 %0, [%1];" : "=r"(v) : "l"(&g_arrive));
            } while (v < target);
        }
        __syncthreads();
    }
}

// ---------------------------------------------------------------------------
extern "C" void kernel_launch(void* const* d_in, const int* in_sizes, int n_in,
                              void* d_out, int out_size)
{
    const float* x     = (const float*)d_in[0];
    const float* W_ih  = (const float*)d_in[1];
    const float* W_hh  = (const float*)d_in[2];
    const float* b_ih  = (const float*)d_in[3];
    const float* b_hh  = (const float*)d_in[4];
    const float* W_out = (const float*)d_in[5];
    const float* b_out = (const float*)d_in[6];
    float* out = (float*)d_out;

    cudaFuncSetAttribute(lstm_kernel,
                         cudaFuncAttributeMaxDynamicSharedMemorySize, SMEM_BYTES);
    prep_kernel<<<1024, 256>>>(x);
    lstm_kernel<<<NCTA, 256, SMEM_BYTES>>>(W_ih, W_hh, b_ih, b_hh, W_out, b_out, out);
}

// round 7
// speedup vs baseline: 1.3057x; 1.0203x over previous
#include <cuda_runtime.h>
#include <cstdint>

#define T_STEPS 512
#define BD 64
#define ID 256
#define HD 1024
#define OD 256
#define NG 4096
#define KD 1280
#define NPC 32
#define NCTA 136
#define KC 64
#define NCHUNK 20
#define NKI 160                         // KD / 8
#define NBUF 4

#define SW_FLOATS (NKI * 2 * 32 * 4)    // 40960 floats = 160KB (W fragments)
#define SS_FLOATS (8 * NBUF * BD * 8)   // 16384 floats = 64KB (per-warp A slices)
#define SMEM_BYTES ((SW_FLOATS + SS_FLOATS) * 4)   // 229376 B
#define RED_PITCH 17                    // reduction row pitch (floats)

// Persistent device scratch (allocation-free rule: __device__ globals)
__device__ float g_xr[(size_t)T_STEPS * BD * ID];  // tf32-rounded x, pair-packed within 8-groups
__device__ float g_h[2][BD * HD];                  // ping-pong hidden state (rounded, pair-packed)
__device__ unsigned g_arrive;                      // grid barrier counter

__device__ __forceinline__ uint32_t f2tf(float f) {
    uint32_t u;
    asm("cvt.rna.tf32.f32 %0, %1;" : "=r"(u) : "f"(f));
    return u;
}
__device__ __forceinline__ float f2tff(float f) { return __uint_as_float(f2tf(f)); }

__device__ __forceinline__ void cpasync16(uint32_t smem, const void* gmem) {
    asm volatile("cp.async.cg.shared.global [%0], [%1], 16;\n" :: "r"(smem), "l"(gmem));
}

// ---------------------------------------------------------------------------
// Prep: rounded+permuted x copy, zero h, reset barrier counter.
// Pair-pack permutation WITHIN each 8-group: offset cg -> 2*(cg&3) + (cg>>2).
// ---------------------------------------------------------------------------
__global__ void prep_kernel(const float* __restrict__ x)
{
    const size_t S_X = (size_t)T_STEPS * BD * ID;
    const size_t S_H = S_X + 2 * BD * HD;
    for (size_t i = (size_t)blockIdx.x * blockDim.x + threadIdx.x; i < S_H;
         i += (size_t)gridDim.x * blockDim.x) {
        if (i == 0) g_arrive = 0;
        if (i < S_X) {
            int c = (int)(i & 255);             // ID == 256
            int cg = c & 7;                     // within-8-group offset
            size_t base = i - (size_t)c;
            g_xr[base + (c & ~7) + 2 * (cg & 3) + (cg >> 2)] = f2tff(x[i]);
        } else {
            ((float*)g_h)[i - S_X] = 0.0f;
        }
    }
}

// ---------------------------------------------------------------------------
// Persistent LSTM kernel. 136 CTAs x 256 threads (8 warps), one CTA per SM.
// CTA b owns gate rows [32b, 32b+32) (reordered r = 4*j+gate) or, for the
// last 8 CTAs, output-projection rows.
// K-SPLIT + DECOUPLED WARPS: warp w owns k8-slices {kc*8+w}; it stages its
// own 64x8 A slice per chunk via per-thread cp.async groups and syncs with
// __syncwarp only -> ZERO __syncthreads in the mainloop. Chunks 0..1 of the
// next step (x-only, h-independent) are prefetched before the grid barrier.
// ---------------------------------------------------------------------------
__global__ void __launch_bounds__(256, 1) lstm_kernel(
    const float* __restrict__ W_ih, const float* __restrict__ W_hh,
    const float* __restrict__ b_ih, const float* __restrict__ b_hh,
    const float* __restrict__ W_out, const float* __restrict__ b_out,
    float* __restrict__ out)
{
    extern __shared__ float sm[];
    float* sW = sm;                    // [NKI][2][32 lanes][4]  (fragment layout)
    float* sS = sm + SW_FLOATS;        // [8 warps][NBUF][64 rows][8]; also reduction buffer

    const int tid = threadIdx.x;
    const int lane = tid & 31, w = tid >> 5;
    const int G = lane >> 2, tg = lane & 3;
    const int n0 = blockIdx.x * NPC;
    const bool is_out = (n0 >= NG);

    // ---- Build W fragments in smem (once). Coalesced float4 row reads. ----
    {
        const int r = tid >> 3;                 // local row 0..31
        const int cth = tid & 7;
        const int rowg = n0 + r;
        const int nt = r >> 3, Gr = r & 7;
#pragma unroll 1
        for (int u = 0; u < KD / 32; u++) {
            int col0 = cth * 4 + u * 32;
            float4 v;
            if (rowg < NG) {
                int orig = (rowg & 3) * HD + (rowg >> 2);   // PyTorch i,f,g,o blocks
                if (col0 < ID) v = *(const float4*)&W_ih[(size_t)orig * ID + col0];
                else           v = *(const float4*)&W_hh[(size_t)orig * HD + (col0 - ID)];
            } else {
                if (col0 < ID) v = make_float4(0.f, 0.f, 0.f, 0.f);
                else           v = *(const float4*)&W_out[(size_t)(rowg - NG) * HD + (col0 - ID)];
            }
            float vv[4] = {v.x, v.y, v.z, v.w};
#pragma unroll
            for (int e = 0; e < 4; e++) {
                int col = col0 + e;
                int ki = col >> 3, cw = col & 7;
                int tgc = cw & 3, half = cw >> 2;
                int idx = ((ki * 2 + (nt >> 1)) * 32 + (Gr * 4 + tgc)) * 4 + (nt & 1) * 2 + half;
                sW[idx] = f2tff(vv[e]);
            }
        }
    }

    // ---- Per-thread epilogue bias: thread (b=tid>>2, u=tid&3), cols 4u+g ----
    float bias[2][4];
#pragma unroll
    for (int hn = 0; hn < 2; hn++) {
#pragma unroll
        for (int g = 0; g < 4; g++) {
            int rr = n0 + hn * 16 + 4 * (tid & 3) + g;
            float bv;
            if (rr < NG) {
                int orig = (rr & 3) * HD + (rr >> 2);
                bv = b_ih[orig] + b_hh[orig];
            } else bv = b_out[rr - NG];
            bias[hn][g] = bv;
        }
    }
    float cstate[2] = {0.0f, 0.0f};    // c for (b, jl=4*hn+u)
    __syncthreads();

    // ---- Per-warp staging: chunk kc's 64x8 slice for this warp ----
    auto stageS = [&](int kc, int tx, const float* __restrict__ hsrc) {
        const int kiG = kc * 8 + w;
        float* dstb = sS + (size_t)(w * NBUF + (kc & 3)) * BD * 8;
        const float* srcb;
        int rstride;
        if (kiG < 32) { srcb = &g_xr[(size_t)tx * BD * ID + kiG * 8]; rstride = ID; }
        else          { srcb = hsrc + (kiG * 8 - ID);                 rstride = HD; }
#pragma unroll
        for (int it = 0; it < 4; it++) {
            int seg = it * 32 + lane;
            int row = seg >> 1, half = seg & 1;
            cpasync16((uint32_t)__cvta_generic_to_shared(dstb + row * 8 + half * 4),
                      srcb + (size_t)row * rstride + half * 4);
        }
    };

    // Initial prefetch for step 0 (gate CTAs only; chunks 0,1 are x-only)
    if (!is_out) {
        stageS(0, 0, g_h[0]); asm volatile("cp.async.commit_group;");
        stageS(1, 0, g_h[0]); asm volatile("cp.async.commit_group;");
    }

    // ---- Time loop ----
    for (int t = 0; t <= T_STEPS; t++) {
        const bool active = is_out ? (t > 0) : (t < T_STEPS);
        if (active) {
            const int tx = (t < T_STEPS) ? t : (T_STEPS - 1);  // W=0 over x-range for out rows
            const float* __restrict__ hsrc = g_h[t & 1];

            float acc[4][4][4];                     // [m-tile][n-tile][frag]
#pragma unroll
            for (int m = 0; m < 4; m++)
#pragma unroll
                for (int n = 0; n < 4; n++)
#pragma unroll
                    for (int e = 0; e < 4; e++) acc[m][n][e] = 0.0f;

            // ---- decoupled mainloop: NO __syncthreads ----
#pragma unroll 1
            for (int kc = 0; kc < NCHUNK; kc++) {
                if (kc + 2 < NCHUNK) stageS(kc + 2, tx, hsrc);
                asm volatile("cp.async.commit_group;");
                asm volatile("cp.async.wait_group 2;");
                __syncwarp();
                const float* buf = sS + (size_t)(w * NBUF + (kc & 3)) * BD * 8;
                const int kiG = kc * 8 + w;         // this warp's k-slice
                float4 B0 = *(const float4*)&sW[((kiG * 2 + 0) * 32 + lane) * 4];
                float4 B1 = *(const float4*)&sW[((kiG * 2 + 1) * 32 + lane) * 4];
#pragma unroll
                for (int m = 0; m < 4; m++) {
                    float2 aL = *(const float2*)&buf[(16 * m + G) * 8 + 2 * tg];
                    float2 aH = *(const float2*)&buf[(16 * m + G + 8) * 8 + 2 * tg];
                    uint32_t a0 = __float_as_uint(aL.x), a2 = __float_as_uint(aL.y);
                    uint32_t a1 = __float_as_uint(aH.x), a3 = __float_as_uint(aH.y);
#define MMA1(ACC, B0R, B1R)                                                     \
    asm volatile(                                                               \
        "mma.sync.aligned.m16n8k8.row.col.f32.tf32.tf32.f32 "                   \
        "{%0,%1,%2,%3},{%4,%5,%6,%7},{%8,%9},{%0,%1,%2,%3};"                    \
        : "+f"(ACC[0]), "+f"(ACC[1]), "+f"(ACC[2]), "+f"(ACC[3])                \
        : "r"(a0), "r"(a1), "r"(a2), "r"(a3), "r"(B0R), "r"(B1R))
                    MMA1(acc[m][0], __float_as_uint(B0.x), __float_as_uint(B0.y));
                    MMA1(acc[m][1], __float_as_uint(B0.z), __float_as_uint(B0.w));
                    MMA1(acc[m][2], __float_as_uint(B1.x), __float_as_uint(B1.y));
                    MMA1(acc[m][3], __float_as_uint(B1.z), __float_as_uint(B1.w));
#undef MMA1
                }
            }
            __syncthreads();    // converge before reduction-buffer reuse

            // ---- 8-way reduction + epilogue, two N-halves of 16 cols ----
            float* sRed = sS;
            const int b = tid >> 2, u = tid & 3;
#pragma unroll 1
            for (int hn = 0; hn < 2; hn++) {
#pragma unroll
                for (int m = 0; m < 4; m++)
#pragma unroll
                    for (int nl = 0; nl < 2; nl++)
#pragma unroll
                        for (int e = 0; e < 4; e++) {
                            int row = 16 * m + G + (e >> 1) * 8;
                            int ch = nl * 8 + 2 * tg + (e & 1);
                            sRed[(w * BD + row) * RED_PITCH + ch] = acc[m][2 * hn + nl][e];
                        }
                __syncthreads();
                float gv[4];
#pragma unroll
                for (int g = 0; g < 4; g++) {
                    float s = 0.0f;
#pragma unroll
                    for (int ww = 0; ww < 8; ww++)
                        s += sRed[(ww * BD + b) * RED_PITCH + 4 * u + g];
                    gv[g] = s + bias[hn][g];
                }
                if (!is_out) {
                    float ig = 1.0f / (1.0f + __expf(-gv[0]));
                    float fg = 1.0f / (1.0f + __expf(-gv[1]));
                    float gg = tanhf(gv[2]);
                    float og = 1.0f / (1.0f + __expf(-gv[3]));
                    float cv = fg * cstate[hn] + ig * gg;
                    cstate[hn] = cv;
                    int jl = 4 * hn + u;
                    int jbase = n0 >> 2;
                    g_h[(t + 1) & 1][b * HD + jbase + 2 * (jl & 3) + (jl >> 2)] =
                        f2tff(og * tanhf(cv));
                } else {
                    float* __restrict__ dst = out + (size_t)(t - 1) * BD * OD;
                    int col = (n0 - NG) + hn * 16 + 4 * u;
                    *(float4*)&dst[(size_t)b * OD + col] =
                        make_float4(gv[0], gv[1], gv[2], gv[3]);
                }
                __syncthreads();
            }
        }

        if (t == T_STEPS) break;

        // ---- prefetch next step's x-only chunks (0,1) BEFORE barrier spin ----
        const bool nact = is_out ? true : (t + 1 < T_STEPS);
        if (nact) {
            int txn = (t + 1 < T_STEPS) ? (t + 1) : (T_STEPS - 1);
            stageS(0, txn, g_h[0]); asm volatile("cp.async.commit_group;");
            stageS(1, txn, g_h[0]); asm volatile("cp.async.commit_group;");
        }

        // ---- grid barrier (136 CTAs co-resident) ----
        __syncthreads();
        if (tid == 0) {
            __threadfence();
            atomicAdd(&g_arrive, 1u);
            const unsigned target = (unsigned)(t + 1) * NCTA;
            unsigned v;
            do {
                asm volatile("ld.acquire.gpu.u32 %0, [%1];" : "=r"(v) : "l"(&g_arrive));
            } while (v < target);
        }
        __syncthreads();
    }
}

// ---------------------------------------------------------------------------
extern "C" void kernel_launch(void* const* d_in, const int* in_sizes, int n_in,
                              void* d_out, int out_size)
{
    const float* x     = (const float*)d_in[0];
    const float* W_ih  = (const float*)d_in[1];
    const float* W_hh  = (const float*)d_in[2];
    const float* b_ih  = (const float*)d_in[3];
    const float* b_hh  = (const float*)d_in[4];
    const float* W_out = (const float*)d_in[5];
    const float* b_out = (const float*)d_in[6];
    float* out = (float*)d_out;

    cudaFuncSetAttribute(lstm_kernel,
                         cudaFuncAttributeMaxDynamicSharedMemorySize, SMEM_BYTES);
    prep_kernel<<<1024, 256>>>(x);
    lstm_kernel<<<NCTA, 256, SMEM_BYTES>>>(W_ih, W_hh, b_ih, b_hh, W_out, b_out, out);
}